// round 9
// baseline (speedup 1.0000x reference)
#include <cuda_runtime.h>
#include <cuda_bf16.h>
#include <stdint.h>

#define N_MAX 50000
#define E_MAX 800000
#define DH 64
#define SCAN_B 256
#define NBLK ((N_MAX + SCAN_B - 1) / SCAN_B)   // 196

// ---------------- device scratch ---------------------------------------------
__device__ __align__(256) float g_bufA[N_MAX * DH];   // xw (GEMM out)
__device__ __align__(256) float g_bufB[N_MAX * DH];   // agg (gather out / next in)
__device__ __align__(16)  float g_dis[N_MAX];
__device__ __align__(16)  int   g_cnt[N_MAX];
__device__ __align__(16)  int   g_fill[N_MAX];
__device__ __align__(16)  int   g_rowptr[N_MAX + 1];
__device__ __align__(16)  int   g_look[NBLK];         // spin-scan mailbox
__device__ __align__(16)  int   g_csrs[E_MAX];        // CSR src indices only

// Per-warp edge-dtype detection: int64 little-endian with values < 2^31 means
// every odd int32 word of the buffer is zero. Reads 64 cached words. ~free.
__device__ __forceinline__ bool detect64(const int* __restrict__ w) {
    int lane = threadIdx.x & 31;
    return __all_sync(0xffffffffu, w[2 * lane + 1] == 0);
}

// ---------------- pass 1: degree histogram (+ zero scan mailbox) ---------------
__global__ void k_hist(const void* __restrict__ ei, int E) {
    bool is64 = detect64((const int*)ei);
    if (blockIdx.x == 0 && threadIdx.x < NBLK) g_look[threadIdx.x] = 0;
    int e = blockIdx.x * blockDim.x + threadIdx.x;
    if (e >= E) return;
    int d;
    if (is64) d = (int)((const long long*)ei)[e + E];
    else      d = ((const int*)ei)[e + E];
    atomicAdd(&g_cnt[d], 1);
}

// ---------------- single-kernel scan: rowptr, dis, fill=0 ----------------------
// Block-local ladder scan; each block publishes its total (flag bit 29) to
// g_look; predecessors' totals are spin-read IN PARALLEL (thread t reads block
// t's mailbox) and block-reduced. All 196 blocks co-resident -> no deadlock.
__global__ __launch_bounds__(SCAN_B) void k_scan(int n, int E) {
    __shared__ int s[SCAN_B];
    int t = threadIdx.x, b = blockIdx.x;
    int i = b * SCAN_B + t;
    int v = (i < n) ? g_cnt[i] : 0;
    s[t] = v;
    __syncthreads();
#pragma unroll
    for (int off = 1; off < SCAN_B; off <<= 1) {
        int add = (t >= off) ? s[t - off] : 0;
        __syncthreads();
        s[t] += add;
        __syncthreads();
    }
    int excl = s[t] - v;
    int btotal = s[SCAN_B - 1];
    if (t == 0) atomicExch(&g_look[b], (1 << 29) | btotal);

    int contrib = 0;
    if (t < b) {                      // one predecessor per thread (b <= 195)
        int w;
        do { w = atomicAdd(&g_look[t], 0); } while (w == 0);
        contrib = w & 0x1FFFFFFF;     // strip flag bit
    }
    __syncthreads();
    s[t] = contrib;
    __syncthreads();
#pragma unroll
    for (int off = 128; off >= 1; off >>= 1) {
        if (t < off) s[t] += s[t + off];
        __syncthreads();
    }
    int base = s[0];

    if (i < n) {
        g_rowptr[i] = base + excl;
        g_dis[i] = rsqrtf((float)(v + 1));
        g_fill[i] = 0;
    }
    if (b == 0 && t == 0) g_rowptr[n] = E;
}

// ---------------- pass 2: CSR fill (src index only) ----------------------------
__global__ void k_fill(const void* __restrict__ ei, int E) {
    const int* w = (const int*)ei;
    bool is64 = detect64(w);
    int e = blockIdx.x * blockDim.x + threadIdx.x;
    if (e >= E) return;
    int s, d;
    if (is64) {
        const long long* p = (const long long*)ei;
        s = (int)p[e];
        d = (int)p[e + E];
    } else {
        s = w[e];
        d = w[e + E];
    }
    int pos = g_rowptr[d] + atomicAdd(&g_fill[d], 1);
    g_csrs[pos] = s;
}

// ---------------- GEMM: out[n,64] = f(in[n,:]) @ W (64x64) ---------------------
template <bool RELU>
__global__ __launch_bounds__(256) void k_gemm64(
    const float* __restrict__ in, float* __restrict__ outp,
    const float* __restrict__ W, const float* __restrict__ bias_in, int n)
{
    __shared__ float Ws[64 * 64];
    __shared__ float bs[64];
    int tid = threadIdx.x;
#pragma unroll
    for (int i = tid; i < 64 * 64 / 4; i += 256)
        ((float4*)Ws)[i] = ((const float4*)W)[i];
    if (RELU && tid < 16) ((float4*)bs)[tid] = ((const float4*)bias_in)[tid];
    __syncthreads();

    int node = blockIdx.x * 64 + (tid >> 2);
    int quad = tid & 3;
    if (node >= n) return;

    float acc[16];
#pragma unroll
    for (int j = 0; j < 16; j++) acc[j] = 0.f;

    const float4* xr4 = (const float4*)(in + (size_t)node * 64);
    for (int k4 = 0; k4 < 16; k4++) {
        float4 v4 = xr4[k4];
        float vv[4] = {v4.x, v4.y, v4.z, v4.w};
#pragma unroll
        for (int u = 0; u < 4; u++) {
            int k = k4 * 4 + u;
            float v = vv[u];
            if (RELU) v = fmaxf(v + bs[k], 0.f);
            const float* wrow = &Ws[k * 64 + quad * 16];
#pragma unroll
            for (int j = 0; j < 16; j++) acc[j] = fmaf(v, wrow[j], acc[j]);
        }
    }
    float* op = outp + (size_t)node * 64 + quad * 16;
#pragma unroll
    for (int j = 0; j < 16; j += 4)
        *(float4*)(op + j) = make_float4(acc[j], acc[j + 1], acc[j + 2], acc[j + 3]);
}

// ---------------- CSR gather (software-pipelined) -------------------------------
// agg[v] = dis[v] * ( dis[v]*xw[v] + sum_s dis[s]*xw[s] )
// 16 threads/node, one float4 column each. Next batch's src indices are
// prefetched before the current batch's FMAs, breaking the csr->feature
// serial dependency (one L2 trip per iteration instead of two).
__global__ __launch_bounds__(256) void k_gather(
    const float* __restrict__ fin, float* __restrict__ fout, int n)
{
    int tid = threadIdx.x;
    int node = blockIdx.x * 16 + (tid >> 4);
    int c = tid & 15;
    if (node >= n) return;

    float dv = g_dis[node];
    const float4* xa = (const float4*)fin;
    float4 me = xa[node * 16 + c];
    float ax = me.x * dv, ay = me.y * dv, az = me.z * dv, aw = me.w * dv;

    int p   = g_rowptr[node];
    int end = g_rowptr[node + 1];

    int s0 = 0, s1 = 0, s2 = 0, s3 = 0;
    if (p + 3 < end) {
        s0 = g_csrs[p]; s1 = g_csrs[p + 1]; s2 = g_csrs[p + 2]; s3 = g_csrs[p + 3];
    }
    while (p + 3 < end) {
        // issue feature + norm loads for the CURRENT batch
        float4 v0 = xa[s0 * 16 + c]; float d0 = g_dis[s0];
        float4 v1 = xa[s1 * 16 + c]; float d1 = g_dis[s1];
        float4 v2 = xa[s2 * 16 + c]; float d2 = g_dis[s2];
        float4 v3 = xa[s3 * 16 + c]; float d3 = g_dis[s3];
        p += 4;
        // prefetch NEXT batch's srcs while the above loads are in flight
        if (p + 3 < end) {
            s0 = g_csrs[p]; s1 = g_csrs[p + 1]; s2 = g_csrs[p + 2]; s3 = g_csrs[p + 3];
        }
        ax = fmaf(v0.x, d0, ax); ay = fmaf(v0.y, d0, ay);
        az = fmaf(v0.z, d0, az); aw = fmaf(v0.w, d0, aw);
        ax = fmaf(v1.x, d1, ax); ay = fmaf(v1.y, d1, ay);
        az = fmaf(v1.z, d1, az); aw = fmaf(v1.w, d1, aw);
        ax = fmaf(v2.x, d2, ax); ay = fmaf(v2.y, d2, ay);
        az = fmaf(v2.z, d2, az); aw = fmaf(v2.w, d2, aw);
        ax = fmaf(v3.x, d3, ax); ay = fmaf(v3.y, d3, ay);
        az = fmaf(v3.z, d3, az); aw = fmaf(v3.w, d3, aw);
    }
    for (; p < end; p++) {
        int s = g_csrs[p];
        float ds = g_dis[s];
        float4 v = xa[s * 16 + c];
        ax = fmaf(v.x, ds, ax); ay = fmaf(v.y, ds, ay);
        az = fmaf(v.z, ds, az); aw = fmaf(v.w, ds, aw);
    }
    ((float4*)fout)[node * 16 + c] =
        make_float4(ax * dv, ay * dv, az * dv, aw * dv);
}

// ---------------- final linear: out = relu(agg2 + b2) @ linW + linb ------------
__global__ __launch_bounds__(256) void k_final(
    const float* __restrict__ fin,
    const float* __restrict__ linW, const float* __restrict__ b2,
    const float* __restrict__ linb, float* __restrict__ out, int n)
{
    __shared__ float Ws[64 * 8];
    __shared__ float bs[64];
    __shared__ float lb[8];
    int tid = threadIdx.x;
#pragma unroll
    for (int i = tid; i < 128; i += 256) ((float4*)Ws)[i] = ((const float4*)linW)[i];
    if (tid < 16) ((float4*)bs)[tid] = ((const float4*)b2)[tid];
    if (tid < 2)  ((float4*)lb)[tid] = ((const float4*)linb)[tid];
    __syncthreads();

    int node = blockIdx.x * blockDim.x + tid;
    if (node >= n) return;

    float acc[8];
#pragma unroll
    for (int j = 0; j < 8; j++) acc[j] = lb[j];

    const float* xr = fin + (size_t)node * 64;
    for (int k = 0; k < 64; k++) {
        float v = fmaxf(xr[k] + bs[k], 0.f);
        const float* wrow = &Ws[k * 8];
#pragma unroll
        for (int j = 0; j < 8; j++) acc[j] = fmaf(v, wrow[j], acc[j]);
    }
    float* op = out + (size_t)node * 8;
#pragma unroll
    for (int j = 0; j < 8; j += 4)
        *(float4*)(op + j) = make_float4(acc[j], acc[j + 1], acc[j + 2], acc[j + 3]);
}

// ---------------- host launcher ------------------------------------------------
extern "C" void kernel_launch(void* const* d_in, const int* in_sizes, int n_in,
                              void* d_out, int out_size)
{
    const float* x    = (const float*)d_in[0];
    const void*  ei   = d_in[1];
    const float* W0   = (const float*)d_in[2];
    const float* b0   = (const float*)d_in[3];
    const float* W1   = (const float*)d_in[4];
    const float* b1   = (const float*)d_in[5];
    const float* W2   = (const float*)d_in[6];
    const float* b2   = (const float*)d_in[7];
    const float* linW = (const float*)d_in[8];
    const float* linb = (const float*)d_in[9];
    float* out = (float*)d_out;

    int N = in_sizes[0] / DH;       // 50000
    int E = in_sizes[1] / 2;        // 800000

    const int T = 256;
    int gN = (N + T - 1) / T;       // 196
    int gE = (E + T - 1) / T;       // 3125
    int gG = (N + 63) / 64;         // 782
    int gA = (N + 15) / 16;         // 3125

    // One-time host-side setup (first call is the uncaptured correctness run).
    static float* bufA = nullptr;
    static float* bufB = nullptr;
    static int*   cntP = nullptr;
    static cudaStream_t s2;
    static cudaEvent_t evFork, evJoin;
    if (!bufA) {
        void* p;
        cudaGetSymbolAddress(&p, g_bufA); bufA = (float*)p;
        cudaGetSymbolAddress(&p, g_bufB); bufB = (float*)p;
        cudaGetSymbolAddress(&p, g_cnt);  cntP = (int*)p;
        cudaStreamCreateWithFlags(&s2, cudaStreamNonBlocking);
        cudaEventCreateWithFlags(&evFork, cudaEventDisableTiming);
        cudaEventCreateWithFlags(&evJoin, cudaEventDisableTiming);
    }

    // Fork: layer-0 GEMM (depends only on x, W0) overlaps the CSR build.
    cudaEventRecord(evFork, 0);
    cudaStreamWaitEvent(s2, evFork, 0);
    k_gemm64<false><<<gG, T, 0, s2>>>(x, bufA, W0, nullptr, N);
    cudaEventRecord(evJoin, s2);

    // CSR build on the main stream.
    cudaMemsetAsync(cntP, 0, (size_t)N * sizeof(int));
    k_hist<<<gE, T>>>(ei, E);
    k_scan<<<gN, SCAN_B>>>(N, E);
    k_fill<<<gE, T>>>(ei, E);

    // Join before the first gather consumes bufA.
    cudaStreamWaitEvent(0, evJoin, 0);

    // layer 0 aggregate
    k_gather<<<gA, T>>>(bufA, bufB, N);
    // layer 1
    k_gemm64<true><<<gG, T>>>(bufB, bufA, W1, b0, N);
    k_gather<<<gA, T>>>(bufA, bufB, N);
    // layer 2
    k_gemm64<true><<<gG, T>>>(bufB, bufA, W2, b1, N);
    k_gather<<<gA, T>>>(bufA, bufB, N);
    // head
    k_final<<<gN, T>>>(bufB, linW, b2, linb, out, N);
}

// round 10
// speedup vs baseline: 1.0537x; 1.0537x over previous
#include <cuda_runtime.h>
#include <cuda_fp16.h>
#include <stdint.h>

#define N_MAX 50000
#define E_MAX 800000
#define DH 64
#define SCAN_B 256
#define NBLK ((N_MAX + SCAN_B - 1) / SCAN_B)   // 196

// ---------------- device scratch ---------------------------------------------
__device__ __align__(256) __half g_bufA[N_MAX * DH];  // xw in fp16 (random-read)
__device__ __align__(256) float  g_bufB[N_MAX * DH];  // agg fp32 (streamed)
__device__ __align__(16)  float g_dis[N_MAX];
__device__ __align__(16)  int   g_cnt[N_MAX];
__device__ __align__(16)  int   g_fill[N_MAX];
__device__ __align__(16)  int   g_rowptr[N_MAX + 1];
__device__ __align__(16)  int   g_look[NBLK];         // spin-scan mailbox
__device__ __align__(16)  int   g_csrs[E_MAX];        // CSR src indices only

// Per-warp edge-dtype detection: int64 little-endian with values < 2^31 means
// every odd int32 word of the buffer is zero.
__device__ __forceinline__ bool detect64(const int* __restrict__ w) {
    int lane = threadIdx.x & 31;
    return __all_sync(0xffffffffu, w[2 * lane + 1] == 0);
}

// ---------------- pass 1: degree histogram (+ zero scan mailbox) ---------------
__global__ void k_hist(const void* __restrict__ ei, int E) {
    bool is64 = detect64((const int*)ei);
    if (blockIdx.x == 0 && threadIdx.x < NBLK) g_look[threadIdx.x] = 0;
    int e = blockIdx.x * blockDim.x + threadIdx.x;
    if (e >= E) return;
    int d;
    if (is64) d = (int)((const long long*)ei)[e + E];
    else      d = ((const int*)ei)[e + E];
    atomicAdd(&g_cnt[d], 1);
}

// ---------------- single-kernel scan: rowptr, dis, fill=0 ----------------------
__global__ __launch_bounds__(SCAN_B) void k_scan(int n, int E) {
    __shared__ int s[SCAN_B];
    int t = threadIdx.x, b = blockIdx.x;
    int i = b * SCAN_B + t;
    int v = (i < n) ? g_cnt[i] : 0;
    s[t] = v;
    __syncthreads();
#pragma unroll
    for (int off = 1; off < SCAN_B; off <<= 1) {
        int add = (t >= off) ? s[t - off] : 0;
        __syncthreads();
        s[t] += add;
        __syncthreads();
    }
    int excl = s[t] - v;
    int btotal = s[SCAN_B - 1];
    if (t == 0) atomicExch(&g_look[b], (1 << 29) | btotal);

    int contrib = 0;
    if (t < b) {
        int w;
        do { w = atomicAdd(&g_look[t], 0); } while (w == 0);
        contrib = w & 0x1FFFFFFF;
    }
    __syncthreads();
    s[t] = contrib;
    __syncthreads();
#pragma unroll
    for (int off = 128; off >= 1; off >>= 1) {
        if (t < off) s[t] += s[t + off];
        __syncthreads();
    }
    int base = s[0];

    if (i < n) {
        g_rowptr[i] = base + excl;
        g_dis[i] = rsqrtf((float)(v + 1));
        g_fill[i] = 0;
    }
    if (b == 0 && t == 0) g_rowptr[n] = E;
}

// ---------------- pass 2: CSR fill (src index only) ----------------------------
__global__ void k_fill(const void* __restrict__ ei, int E) {
    const int* w = (const int*)ei;
    bool is64 = detect64(w);
    int e = blockIdx.x * blockDim.x + threadIdx.x;
    if (e >= E) return;
    int s, d;
    if (is64) {
        const long long* p = (const long long*)ei;
        s = (int)p[e];
        d = (int)p[e + E];
    } else {
        s = w[e];
        d = w[e + E];
    }
    int pos = g_rowptr[d] + atomicAdd(&g_fill[d], 1);
    g_csrs[pos] = s;
}

// ---------------- GEMM: out_h[n,64] = f(in[n,:]) @ W, stored fp16 --------------
// f = relu(v + bias_in) when RELU. 4 threads/node, 16 output cols each.
template <bool RELU>
__global__ __launch_bounds__(256) void k_gemm64(
    const float* __restrict__ in, __half* __restrict__ outp,
    const float* __restrict__ W, const float* __restrict__ bias_in, int n)
{
    __shared__ float Ws[64 * 64];
    __shared__ float bs[64];
    int tid = threadIdx.x;
#pragma unroll
    for (int i = tid; i < 64 * 64 / 4; i += 256)
        ((float4*)Ws)[i] = ((const float4*)W)[i];
    if (RELU && tid < 16) ((float4*)bs)[tid] = ((const float4*)bias_in)[tid];
    __syncthreads();

    int node = blockIdx.x * 64 + (tid >> 2);
    int quad = tid & 3;
    if (node >= n) return;

    float acc[16];
#pragma unroll
    for (int j = 0; j < 16; j++) acc[j] = 0.f;

    const float4* xr4 = (const float4*)(in + (size_t)node * 64);
    for (int k4 = 0; k4 < 16; k4++) {
        float4 v4 = xr4[k4];
        float vv[4] = {v4.x, v4.y, v4.z, v4.w};
#pragma unroll
        for (int u = 0; u < 4; u++) {
            int k = k4 * 4 + u;
            float v = vv[u];
            if (RELU) v = fmaxf(v + bs[k], 0.f);
            const float* wrow = &Ws[k * 64 + quad * 16];
#pragma unroll
            for (int j = 0; j < 16; j++) acc[j] = fmaf(v, wrow[j], acc[j]);
        }
    }
    // convert to fp16 and store 16 halves (32 B) as two uint4
    half2 h[8];
#pragma unroll
    for (int j = 0; j < 8; j++)
        h[j] = __float22half2_rn(make_float2(acc[2 * j], acc[2 * j + 1]));
    uint4* op = (uint4*)(outp + (size_t)node * 64 + quad * 16);
    op[0] = *(uint4*)&h[0];
    op[1] = *(uint4*)&h[4];
}

// ---------------- CSR gather (fp16 rows, 8 lanes/node) --------------------------
// agg[v] = dis[v] * ( dis[v]*xw[v] + sum_s dis[s]*xw[s] ), accumulated fp32.
// One 128B row = ONE cache line; lane c reads 16B (8 halves). 4-edge batches
// with src-index prefetch.
__device__ __forceinline__ void h8acc(uint4 u, float d, float acc[8]) {
    float2 f0 = __half22float2(*(const half2*)&u.x);
    float2 f1 = __half22float2(*(const half2*)&u.y);
    float2 f2 = __half22float2(*(const half2*)&u.z);
    float2 f3 = __half22float2(*(const half2*)&u.w);
    acc[0] = fmaf(f0.x, d, acc[0]); acc[1] = fmaf(f0.y, d, acc[1]);
    acc[2] = fmaf(f1.x, d, acc[2]); acc[3] = fmaf(f1.y, d, acc[3]);
    acc[4] = fmaf(f2.x, d, acc[4]); acc[5] = fmaf(f2.y, d, acc[5]);
    acc[6] = fmaf(f3.x, d, acc[6]); acc[7] = fmaf(f3.y, d, acc[7]);
}

__global__ __launch_bounds__(256) void k_gather(
    const __half* __restrict__ fin, float* __restrict__ fout, int n)
{
    int tid = threadIdx.x;
    int node = blockIdx.x * 32 + (tid >> 3);
    int c = tid & 7;
    if (node >= n) return;

    float dv = g_dis[node];
    const uint4* xa = (const uint4*)fin;      // one uint4 = 8 halves

    float acc[8];
    {
        uint4 me = xa[node * 8 + c];
        float2 f0 = __half22float2(*(const half2*)&me.x);
        float2 f1 = __half22float2(*(const half2*)&me.y);
        float2 f2 = __half22float2(*(const half2*)&me.z);
        float2 f3 = __half22float2(*(const half2*)&me.w);
        acc[0] = f0.x * dv; acc[1] = f0.y * dv;
        acc[2] = f1.x * dv; acc[3] = f1.y * dv;
        acc[4] = f2.x * dv; acc[5] = f2.y * dv;
        acc[6] = f3.x * dv; acc[7] = f3.y * dv;
    }

    int p   = g_rowptr[node];
    int end = g_rowptr[node + 1];

    int s0 = 0, s1 = 0, s2 = 0, s3 = 0;
    if (p + 3 < end) {
        s0 = g_csrs[p]; s1 = g_csrs[p + 1]; s2 = g_csrs[p + 2]; s3 = g_csrs[p + 3];
    }
    while (p + 3 < end) {
        uint4 v0 = xa[s0 * 8 + c]; float d0 = g_dis[s0];
        uint4 v1 = xa[s1 * 8 + c]; float d1 = g_dis[s1];
        uint4 v2 = xa[s2 * 8 + c]; float d2 = g_dis[s2];
        uint4 v3 = xa[s3 * 8 + c]; float d3 = g_dis[s3];
        p += 4;
        if (p + 3 < end) {   // prefetch next batch's srcs
            s0 = g_csrs[p]; s1 = g_csrs[p + 1]; s2 = g_csrs[p + 2]; s3 = g_csrs[p + 3];
        }
        h8acc(v0, d0, acc);
        h8acc(v1, d1, acc);
        h8acc(v2, d2, acc);
        h8acc(v3, d3, acc);
    }
    for (; p < end; p++) {
        int s = g_csrs[p];
        h8acc(xa[s * 8 + c], g_dis[s], acc);
    }

    float* op = fout + (size_t)node * 64 + c * 8;
    *(float4*)op = make_float4(acc[0] * dv, acc[1] * dv, acc[2] * dv, acc[3] * dv);
    *(float4*)(op + 4) = make_float4(acc[4] * dv, acc[5] * dv, acc[6] * dv, acc[7] * dv);
}

// ---------------- final linear: out = relu(agg2 + b2) @ linW + linb ------------
__global__ __launch_bounds__(256) void k_final(
    const float* __restrict__ fin,
    const float* __restrict__ linW, const float* __restrict__ b2,
    const float* __restrict__ linb, float* __restrict__ out, int n)
{
    __shared__ float Ws[64 * 8];
    __shared__ float bs[64];
    __shared__ float lb[8];
    int tid = threadIdx.x;
#pragma unroll
    for (int i = tid; i < 128; i += 256) ((float4*)Ws)[i] = ((const float4*)linW)[i];
    if (tid < 16) ((float4*)bs)[tid] = ((const float4*)b2)[tid];
    if (tid < 2)  ((float4*)lb)[tid] = ((const float4*)linb)[tid];
    __syncthreads();

    int node = blockIdx.x * blockDim.x + tid;
    if (node >= n) return;

    float acc[8];
#pragma unroll
    for (int j = 0; j < 8; j++) acc[j] = lb[j];

    const float* xr = fin + (size_t)node * 64;
    for (int k = 0; k < 64; k++) {
        float v = fmaxf(xr[k] + bs[k], 0.f);
        const float* wrow = &Ws[k * 8];
#pragma unroll
        for (int j = 0; j < 8; j++) acc[j] = fmaf(v, wrow[j], acc[j]);
    }
    float* op = out + (size_t)node * 8;
#pragma unroll
    for (int j = 0; j < 8; j += 4)
        *(float4*)(op + j) = make_float4(acc[j], acc[j + 1], acc[j + 2], acc[j + 3]);
}

// ---------------- host launcher ------------------------------------------------
extern "C" void kernel_launch(void* const* d_in, const int* in_sizes, int n_in,
                              void* d_out, int out_size)
{
    const float* x    = (const float*)d_in[0];
    const void*  ei   = d_in[1];
    const float* W0   = (const float*)d_in[2];
    const float* b0   = (const float*)d_in[3];
    const float* W1   = (const float*)d_in[4];
    const float* b1   = (const float*)d_in[5];
    const float* W2   = (const float*)d_in[6];
    const float* b2   = (const float*)d_in[7];
    const float* linW = (const float*)d_in[8];
    const float* linb = (const float*)d_in[9];
    float* out = (float*)d_out;

    int N = in_sizes[0] / DH;       // 50000
    int E = in_sizes[1] / 2;        // 800000

    const int T = 256;
    int gN = (N + T - 1) / T;       // 196
    int gE = (E + T - 1) / T;       // 3125
    int gG = (N + 63) / 64;         // 782
    int gA = (N + 31) / 32;         // 1563 (gather: 32 nodes/block)

    // One-time host-side setup (first call is the uncaptured correctness run).
    static __half* bufA = nullptr;
    static float*  bufB = nullptr;
    static int*    cntP = nullptr;
    static cudaStream_t s2;
    static cudaEvent_t evFork, evJoin;
    if (!bufA) {
        void* p;
        cudaGetSymbolAddress(&p, g_bufA); bufA = (__half*)p;
        cudaGetSymbolAddress(&p, g_bufB); bufB = (float*)p;
        cudaGetSymbolAddress(&p, g_cnt);  cntP = (int*)p;
        cudaStreamCreateWithFlags(&s2, cudaStreamNonBlocking);
        cudaEventCreateWithFlags(&evFork, cudaEventDisableTiming);
        cudaEventCreateWithFlags(&evJoin, cudaEventDisableTiming);
    }

    // Fork: layer-0 GEMM (depends only on x, W0) overlaps the CSR build.
    cudaEventRecord(evFork, 0);
    cudaStreamWaitEvent(s2, evFork, 0);
    k_gemm64<false><<<gG, T, 0, s2>>>(x, bufA, W0, nullptr, N);
    cudaEventRecord(evJoin, s2);

    // CSR build on the main stream.
    cudaMemsetAsync(cntP, 0, (size_t)N * sizeof(int));
    k_hist<<<gE, T>>>(ei, E);
    k_scan<<<gN, SCAN_B>>>(N, E);
    k_fill<<<gE, T>>>(ei, E);

    // Join before the first gather consumes bufA.
    cudaStreamWaitEvent(0, evJoin, 0);

    // layer 0 aggregate
    k_gather<<<gA, T>>>(bufA, bufB, N);
    // layer 1
    k_gemm64<true><<<gG, T>>>(bufB, bufA, W1, b0, N);
    k_gather<<<gA, T>>>(bufA, bufB, N);
    // layer 2
    k_gemm64<true><<<gG, T>>>(bufB, bufA, W2, b1, N);
    k_gather<<<gA, T>>>(bufA, bufB, N);
    // head
    k_final<<<gN, T>>>(bufB, linW, b2, linb, out, N);
}

// round 11
// speedup vs baseline: 1.0809x; 1.0258x over previous
#include <cuda_runtime.h>
#include <cuda_fp16.h>
#include <stdint.h>

#define N_MAX 50000
#define E_MAX 800000
#define DH 64
#define SCAN_B 256
#define NBLK ((N_MAX + SCAN_B - 1) / SCAN_B)   // 196
#define GEMM_BLOCKS ((N_MAX + 63) / 64)        // 782

// ---------------- device scratch ---------------------------------------------
__device__ __align__(256) __half g_bufA[N_MAX * DH];  // xw fp16 (random-read)
__device__ __align__(256) float  g_bufB[N_MAX * DH];  // agg fp32 (streamed)
__device__ __align__(16)  float g_dis[N_MAX];
__device__ __align__(16)  int   g_cnt[N_MAX];
__device__ __align__(16)  int   g_fill[N_MAX];
__device__ __align__(16)  int   g_rowptr[N_MAX + 1];
__device__ __align__(16)  int   g_look[NBLK];         // spin-scan mailbox
__device__ __align__(16)  int   g_csrs[E_MAX];        // CSR src indices only

// Per-warp edge-dtype detection: int64 little-endian with values < 2^31 means
// every odd int32 word of the buffer is zero.
__device__ __forceinline__ bool detect64(const int* __restrict__ w) {
    int lane = threadIdx.x & 31;
    return __all_sync(0xffffffffu, w[2 * lane + 1] == 0);
}

// ---------------- fused launch #1: layer-0 GEMM + degree histogram -------------
// Blocks [0, GEMM_BLOCKS): g_bufA = x @ W0 (fp16 store).
// Blocks [GEMM_BLOCKS, ...): degree histogram of dst (+ zero scan mailbox).
// The two halves touch disjoint data; fusing keeps them overlapped without a
// stream fork and makes k_gather the 4th kernel launch (ncu capture target).
__global__ __launch_bounds__(256) void k_gemm0_hist(
    const float* __restrict__ x, const float* __restrict__ W0,
    const void* __restrict__ ei, int n, int E)
{
    __shared__ float Ws[64 * 64];
    int tid = threadIdx.x;

    if (blockIdx.x < GEMM_BLOCKS) {
        // ---- layer-0 GEMM path ----
#pragma unroll
        for (int i = tid; i < 64 * 64 / 4; i += 256)
            ((float4*)Ws)[i] = ((const float4*)W0)[i];
        __syncthreads();

        int node = blockIdx.x * 64 + (tid >> 2);
        int quad = tid & 3;
        if (node >= n) return;

        float acc[16];
#pragma unroll
        for (int j = 0; j < 16; j++) acc[j] = 0.f;

        const float4* xr4 = (const float4*)(x + (size_t)node * 64);
        for (int k4 = 0; k4 < 16; k4++) {
            float4 v4 = xr4[k4];
            float vv[4] = {v4.x, v4.y, v4.z, v4.w};
#pragma unroll
            for (int u = 0; u < 4; u++) {
                const float* wrow = &Ws[(k4 * 4 + u) * 64 + quad * 16];
#pragma unroll
                for (int j = 0; j < 16; j++) acc[j] = fmaf(vv[u], wrow[j], acc[j]);
            }
        }
        half2 h[8];
#pragma unroll
        for (int j = 0; j < 8; j++)
            h[j] = __float22half2_rn(make_float2(acc[2 * j], acc[2 * j + 1]));
        uint4* op = (uint4*)(g_bufA + (size_t)node * 64 + quad * 16);
        op[0] = *(uint4*)&h[0];
        op[1] = *(uint4*)&h[4];
    } else {
        // ---- histogram path ----
        int b = blockIdx.x - GEMM_BLOCKS;
        bool is64 = detect64((const int*)ei);
        if (b == 0 && tid < NBLK) g_look[tid] = 0;
        int e = b * 256 + tid;
        if (e >= E) return;
        int d;
        if (is64) d = (int)((const long long*)ei)[e + E];
        else      d = ((const int*)ei)[e + E];
        atomicAdd(&g_cnt[d], 1);
    }
}

// ---------------- launch #2: single-kernel scan: rowptr, dis, fill=0 ----------
__global__ __launch_bounds__(SCAN_B) void k_scan(int n, int E) {
    __shared__ int s[SCAN_B];
    int t = threadIdx.x, b = blockIdx.x;
    int i = b * SCAN_B + t;
    int v = (i < n) ? g_cnt[i] : 0;
    s[t] = v;
    __syncthreads();
#pragma unroll
    for (int off = 1; off < SCAN_B; off <<= 1) {
        int add = (t >= off) ? s[t - off] : 0;
        __syncthreads();
        s[t] += add;
        __syncthreads();
    }
    int excl = s[t] - v;
    int btotal = s[SCAN_B - 1];
    if (t == 0) atomicExch(&g_look[b], (1 << 29) | btotal);

    int contrib = 0;
    if (t < b) {
        int w;
        do { w = atomicAdd(&g_look[t], 0); } while (w == 0);
        contrib = w & 0x1FFFFFFF;
    }
    __syncthreads();
    s[t] = contrib;
    __syncthreads();
#pragma unroll
    for (int off = 128; off >= 1; off >>= 1) {
        if (t < off) s[t] += s[t + off];
        __syncthreads();
    }
    int base = s[0];

    if (i < n) {
        g_rowptr[i] = base + excl;
        g_dis[i] = rsqrtf((float)(v + 1));
        g_fill[i] = 0;
    }
    if (b == 0 && t == 0) g_rowptr[n] = E;
}

// ---------------- launch #3: CSR fill (src index only) --------------------------
__global__ void k_fill(const void* __restrict__ ei, int E) {
    const int* w = (const int*)ei;
    bool is64 = detect64(w);
    int e = blockIdx.x * blockDim.x + threadIdx.x;
    if (e >= E) return;
    int s, d;
    if (is64) {
        const long long* p = (const long long*)ei;
        s = (int)p[e];
        d = (int)p[e + E];
    } else {
        s = w[e];
        d = w[e + E];
    }
    int pos = g_rowptr[d] + atomicAdd(&g_fill[d], 1);
    g_csrs[pos] = s;
}

// ---------------- launch #4 (ncu capture): CSR gather ---------------------------
// agg[v] = dis[v] * ( dis[v]*xw[v] + sum_s dis[s]*xw[s] ), fp32 accum.
// Reads fp16 g_bufA (one 128B line/row), writes fp32 g_bufB. 8 lanes/node.
// Body identical to round 10 for a clean profile.
__device__ __forceinline__ void h8acc(uint4 u, float d, float acc[8]) {
    float2 f0 = __half22float2(*(const half2*)&u.x);
    float2 f1 = __half22float2(*(const half2*)&u.y);
    float2 f2 = __half22float2(*(const half2*)&u.z);
    float2 f3 = __half22float2(*(const half2*)&u.w);
    acc[0] = fmaf(f0.x, d, acc[0]); acc[1] = fmaf(f0.y, d, acc[1]);
    acc[2] = fmaf(f1.x, d, acc[2]); acc[3] = fmaf(f1.y, d, acc[3]);
    acc[4] = fmaf(f2.x, d, acc[4]); acc[5] = fmaf(f2.y, d, acc[5]);
    acc[6] = fmaf(f3.x, d, acc[6]); acc[7] = fmaf(f3.y, d, acc[7]);
}

__global__ __launch_bounds__(256) void k_gather(int n) {
    int tid = threadIdx.x;
    int node = blockIdx.x * 32 + (tid >> 3);
    int c = tid & 7;
    if (node >= n) return;

    float dv = g_dis[node];
    const uint4* xa = (const uint4*)g_bufA;

    float acc[8];
    {
        uint4 me = xa[node * 8 + c];
        float2 f0 = __half22float2(*(const half2*)&me.x);
        float2 f1 = __half22float2(*(const half2*)&me.y);
        float2 f2 = __half22float2(*(const half2*)&me.z);
        float2 f3 = __half22float2(*(const half2*)&me.w);
        acc[0] = f0.x * dv; acc[1] = f0.y * dv;
        acc[2] = f1.x * dv; acc[3] = f1.y * dv;
        acc[4] = f2.x * dv; acc[5] = f2.y * dv;
        acc[6] = f3.x * dv; acc[7] = f3.y * dv;
    }

    int p   = g_rowptr[node];
    int end = g_rowptr[node + 1];

    int s0 = 0, s1 = 0, s2 = 0, s3 = 0;
    if (p + 3 < end) {
        s0 = g_csrs[p]; s1 = g_csrs[p + 1]; s2 = g_csrs[p + 2]; s3 = g_csrs[p + 3];
    }
    while (p + 3 < end) {
        uint4 v0 = xa[s0 * 8 + c]; float d0 = g_dis[s0];
        uint4 v1 = xa[s1 * 8 + c]; float d1 = g_dis[s1];
        uint4 v2 = xa[s2 * 8 + c]; float d2 = g_dis[s2];
        uint4 v3 = xa[s3 * 8 + c]; float d3 = g_dis[s3];
        p += 4;
        if (p + 3 < end) {
            s0 = g_csrs[p]; s1 = g_csrs[p + 1]; s2 = g_csrs[p + 2]; s3 = g_csrs[p + 3];
        }
        h8acc(v0, d0, acc);
        h8acc(v1, d1, acc);
        h8acc(v2, d2, acc);
        h8acc(v3, d3, acc);
    }
    for (; p < end; p++) {
        int s = g_csrs[p];
        h8acc(xa[s * 8 + c], g_dis[s], acc);
    }

    float* op = g_bufB + (size_t)node * 64 + c * 8;
    *(float4*)op = make_float4(acc[0] * dv, acc[1] * dv, acc[2] * dv, acc[3] * dv);
    *(float4*)(op + 4) = make_float4(acc[4] * dv, acc[5] * dv, acc[6] * dv, acc[7] * dv);
}

// ---------------- hidden GEMM: g_bufA = relu(g_bufB + b) @ W (fp16 store) -------
__global__ __launch_bounds__(256) void k_gemm64(
    const float* __restrict__ W, const float* __restrict__ bias_in, int n)
{
    __shared__ float Ws[64 * 64];
    __shared__ float bs[64];
    int tid = threadIdx.x;
#pragma unroll
    for (int i = tid; i < 64 * 64 / 4; i += 256)
        ((float4*)Ws)[i] = ((const float4*)W)[i];
    if (tid < 16) ((float4*)bs)[tid] = ((const float4*)bias_in)[tid];
    __syncthreads();

    int node = blockIdx.x * 64 + (tid >> 2);
    int quad = tid & 3;
    if (node >= n) return;

    float acc[16];
#pragma unroll
    for (int j = 0; j < 16; j++) acc[j] = 0.f;

    const float4* xr4 = (const float4*)(g_bufB + (size_t)node * 64);
    for (int k4 = 0; k4 < 16; k4++) {
        float4 v4 = xr4[k4];
        float vv[4] = {v4.x, v4.y, v4.z, v4.w};
#pragma unroll
        for (int u = 0; u < 4; u++) {
            int k = k4 * 4 + u;
            float v = fmaxf(vv[u] + bs[k], 0.f);
            const float* wrow = &Ws[k * 64 + quad * 16];
#pragma unroll
            for (int j = 0; j < 16; j++) acc[j] = fmaf(v, wrow[j], acc[j]);
        }
    }
    half2 h[8];
#pragma unroll
    for (int j = 0; j < 8; j++)
        h[j] = __float22half2_rn(make_float2(acc[2 * j], acc[2 * j + 1]));
    uint4* op = (uint4*)(g_bufA + (size_t)node * 64 + quad * 16);
    op[0] = *(uint4*)&h[0];
    op[1] = *(uint4*)&h[4];
}

// ---------------- final linear: out = relu(g_bufB + b2) @ linW + linb -----------
__global__ __launch_bounds__(256) void k_final(
    const float* __restrict__ linW, const float* __restrict__ b2,
    const float* __restrict__ linb, float* __restrict__ out, int n)
{
    __shared__ float Ws[64 * 8];
    __shared__ float bs[64];
    __shared__ float lb[8];
    int tid = threadIdx.x;
#pragma unroll
    for (int i = tid; i < 128; i += 256) ((float4*)Ws)[i] = ((const float4*)linW)[i];
    if (tid < 16) ((float4*)bs)[tid] = ((const float4*)b2)[tid];
    if (tid < 2)  ((float4*)lb)[tid] = ((const float4*)linb)[tid];
    __syncthreads();

    int node = blockIdx.x * blockDim.x + tid;
    if (node >= n) return;

    float acc[8];
#pragma unroll
    for (int j = 0; j < 8; j++) acc[j] = lb[j];

    const float* xr = g_bufB + (size_t)node * 64;
    for (int k = 0; k < 64; k++) {
        float v = fmaxf(xr[k] + bs[k], 0.f);
        const float* wrow = &Ws[k * 8];
#pragma unroll
        for (int j = 0; j < 8; j++) acc[j] = fmaf(v, wrow[j], acc[j]);
    }
    float* op = out + (size_t)node * 8;
#pragma unroll
    for (int j = 0; j < 8; j += 4)
        *(float4*)(op + j) = make_float4(acc[j], acc[j + 1], acc[j + 2], acc[j + 3]);
}

// ---------------- host launcher ------------------------------------------------
extern "C" void kernel_launch(void* const* d_in, const int* in_sizes, int n_in,
                              void* d_out, int out_size)
{
    const float* x    = (const float*)d_in[0];
    const void*  ei   = d_in[1];
    const float* W0   = (const float*)d_in[2];
    const float* b0   = (const float*)d_in[3];
    const float* W1   = (const float*)d_in[4];
    const float* b1   = (const float*)d_in[5];
    const float* W2   = (const float*)d_in[6];
    const float* b2   = (const float*)d_in[7];
    const float* linW = (const float*)d_in[8];
    const float* linb = (const float*)d_in[9];
    float* out = (float*)d_out;

    int N = in_sizes[0] / DH;       // 50000
    int E = in_sizes[1] / 2;        // 800000

    const int T = 256;
    int gN = (N + T - 1) / T;       // 196
    int gE = (E + T - 1) / T;       // 3125
    int gA = (N + 31) / 32;         // 1563

    static int* cntP = nullptr;
    if (!cntP) {
        void* p;
        cudaGetSymbolAddress(&p, g_cnt);
        cntP = (int*)p;
    }
    cudaMemsetAsync(cntP, 0, (size_t)N * sizeof(int));

    // #1: fused layer-0 GEMM + degree histogram (independent block groups)
    k_gemm0_hist<<<GEMM_BLOCKS + gE, T>>>(x, W0, ei, N, E);
    // #2: scan -> rowptr, dis, fill=0
    k_scan<<<gN, SCAN_B>>>(N, E);
    // #3: CSR fill
    k_fill<<<gE, T>>>(ei, E);
    // #4: gather layer 0   <-- ncu capture lands here
    k_gather<<<gA, T>>>(N);
    // layers 1-2 + head
    k_gemm64<<<GEMM_BLOCKS, T>>>(W1, b0, N);
    k_gather<<<gA, T>>>(N);
    k_gemm64<<<GEMM_BLOCKS, T>>>(W2, b1, N);
    k_gather<<<gA, T>>>(N);
    k_final<<<gN, T>>>(linW, b2, linb, out, N);
}

// round 12
// speedup vs baseline: 1.2375x; 1.1449x over previous
#include <cuda_runtime.h>
#include <cuda_fp16.h>
#include <stdint.h>

#define N_MAX 50000
#define E_MAX 800000
#define DH 64
#define SCAN_B 256
#define NBLK ((N_MAX + SCAN_B - 1) / SCAN_B)   // 196
#define GEMM_BLOCKS ((N_MAX + 63) / 64)        // 782

// ---------------- device scratch ---------------------------------------------
__device__ __align__(256) __half g_bufA[N_MAX * DH];  // fp16 features (ping)
__device__ __align__(256) __half g_bufC[N_MAX * DH];  // fp16 features (pong)
__device__ __align__(16)  float g_dis[N_MAX];
__device__ __align__(16)  int   g_cnt[N_MAX];
__device__ __align__(16)  int   g_rowptr[N_MAX + 1];
__device__ __align__(16)  int   g_look[NBLK];         // spin-scan mailbox
__device__ __align__(16)  int   g_slot[E_MAX];        // per-edge slot in its row
__device__ __align__(16)  int   g_csrs[E_MAX];        // CSR src indices

// Per-warp edge-dtype detection: int64 little-endian with values < 2^31 means
// every odd int32 word of the buffer is zero.
__device__ __forceinline__ bool detect64(const int* __restrict__ w) {
    int lane = threadIdx.x & 31;
    return __all_sync(0xffffffffu, w[2 * lane + 1] == 0);
}

// ---------------- launch #1: fused layer-0 GEMM + degree histogram -------------
// Blocks [0, GEMM_BLOCKS): g_bufA = x @ W0 (fp16).
// Blocks [GEMM_BLOCKS, ..): histogram; the atomic's return value is the edge's
// slot within its destination row (saved to g_slot -> fill needs NO atomics).
__global__ __launch_bounds__(256) void k_gemm0_hist(
    const float* __restrict__ x, const float* __restrict__ W0,
    const void* __restrict__ ei, int n, int E)
{
    __shared__ float Ws[64 * 64];
    int tid = threadIdx.x;

    if (blockIdx.x < GEMM_BLOCKS) {
#pragma unroll
        for (int i = tid; i < 64 * 64 / 4; i += 256)
            ((float4*)Ws)[i] = ((const float4*)W0)[i];
        __syncthreads();

        int node = blockIdx.x * 64 + (tid >> 2);
        int quad = tid & 3;
        if (node >= n) return;

        float acc[16];
#pragma unroll
        for (int j = 0; j < 16; j++) acc[j] = 0.f;

        const float4* xr4 = (const float4*)(x + (size_t)node * 64);
        for (int k4 = 0; k4 < 16; k4++) {
            float4 v4 = xr4[k4];
            float vv[4] = {v4.x, v4.y, v4.z, v4.w};
#pragma unroll
            for (int u = 0; u < 4; u++) {
                const float* wrow = &Ws[(k4 * 4 + u) * 64 + quad * 16];
#pragma unroll
                for (int j = 0; j < 16; j++) acc[j] = fmaf(vv[u], wrow[j], acc[j]);
            }
        }
        half2 h[8];
#pragma unroll
        for (int j = 0; j < 8; j++)
            h[j] = __float22half2_rn(make_float2(acc[2 * j], acc[2 * j + 1]));
        uint4* op = (uint4*)(g_bufA + (size_t)node * 64 + quad * 16);
        op[0] = *(uint4*)&h[0];
        op[1] = *(uint4*)&h[4];
    } else {
        int b = blockIdx.x - GEMM_BLOCKS;
        bool is64 = detect64((const int*)ei);
        if (b == 0 && tid < NBLK) g_look[tid] = 0;
        int e = b * 256 + tid;
        if (e >= E) return;
        int d;
        if (is64) d = (int)((const long long*)ei)[e + E];
        else      d = ((const int*)ei)[e + E];
        g_slot[e] = atomicAdd(&g_cnt[d], 1);
    }
}

// ---------------- launch #2: single-kernel scan: rowptr, dis -------------------
__global__ __launch_bounds__(SCAN_B) void k_scan(int n, int E) {
    __shared__ int s[SCAN_B];
    int t = threadIdx.x, b = blockIdx.x;
    int i = b * SCAN_B + t;
    int v = (i < n) ? g_cnt[i] : 0;
    s[t] = v;
    __syncthreads();
#pragma unroll
    for (int off = 1; off < SCAN_B; off <<= 1) {
        int add = (t >= off) ? s[t - off] : 0;
        __syncthreads();
        s[t] += add;
        __syncthreads();
    }
    int excl = s[t] - v;
    int btotal = s[SCAN_B - 1];
    if (t == 0) atomicExch(&g_look[b], (1 << 29) | btotal);

    int contrib = 0;
    if (t < b) {
        int w;
        do { w = atomicAdd(&g_look[t], 0); } while (w == 0);
        contrib = w & 0x1FFFFFFF;
    }
    __syncthreads();
    s[t] = contrib;
    __syncthreads();
#pragma unroll
    for (int off = 128; off >= 1; off >>= 1) {
        if (t < off) s[t] += s[t + off];
        __syncthreads();
    }
    int base = s[0];

    if (i < n) {
        g_rowptr[i] = base + excl;
        g_dis[i] = rsqrtf((float)(v + 1));
    }
    if (b == 0 && t == 0) g_rowptr[n] = E;
}

// ---------------- launch #3: CSR fill (atomic-free) ----------------------------
__global__ void k_fill(const void* __restrict__ ei, int E) {
    const int* w = (const int*)ei;
    bool is64 = detect64(w);
    int e = blockIdx.x * blockDim.x + threadIdx.x;
    if (e >= E) return;
    int s, d;
    if (is64) {
        const long long* p = (const long long*)ei;
        s = (int)p[e];
        d = (int)p[e + E];
    } else {
        s = w[e];
        d = w[e + E];
    }
    g_csrs[g_rowptr[d] + g_slot[e]] = s;
}

// ---------------- fp16 helpers --------------------------------------------------
__device__ __forceinline__ void h8acc(uint4 u, float d, float acc[8]) {
    float2 f0 = __half22float2(*(const half2*)&u.x);
    float2 f1 = __half22float2(*(const half2*)&u.y);
    float2 f2 = __half22float2(*(const half2*)&u.z);
    float2 f3 = __half22float2(*(const half2*)&u.w);
    acc[0] = fmaf(f0.x, d, acc[0]); acc[1] = fmaf(f0.y, d, acc[1]);
    acc[2] = fmaf(f1.x, d, acc[2]); acc[3] = fmaf(f1.y, d, acc[3]);
    acc[4] = fmaf(f2.x, d, acc[4]); acc[5] = fmaf(f2.y, d, acc[5]);
    acc[6] = fmaf(f3.x, d, acc[6]); acc[7] = fmaf(f3.y, d, acc[7]);
}

// Gather one node-column: acc = dv*xw[v] + sum_s dis[s]*xw[s], fp32 accum.
__device__ __forceinline__ void gather8(
    const uint4* __restrict__ xa, int node, int c, float dv, float acc[8])
{
    uint4 me = xa[node * 8 + c];
    float2 f0 = __half22float2(*(const half2*)&me.x);
    float2 f1 = __half22float2(*(const half2*)&me.y);
    float2 f2 = __half22float2(*(const half2*)&me.z);
    float2 f3 = __half22float2(*(const half2*)&me.w);
    acc[0] = f0.x * dv; acc[1] = f0.y * dv;
    acc[2] = f1.x * dv; acc[3] = f1.y * dv;
    acc[4] = f2.x * dv; acc[5] = f2.y * dv;
    acc[6] = f3.x * dv; acc[7] = f3.y * dv;

    int p   = g_rowptr[node];
    int end = g_rowptr[node + 1];

    int s0 = 0, s1 = 0, s2 = 0, s3 = 0;
    if (p + 3 < end) {
        s0 = g_csrs[p]; s1 = g_csrs[p + 1]; s2 = g_csrs[p + 2]; s3 = g_csrs[p + 3];
    }
    while (p + 3 < end) {
        uint4 v0 = xa[s0 * 8 + c]; float d0 = g_dis[s0];
        uint4 v1 = xa[s1 * 8 + c]; float d1 = g_dis[s1];
        uint4 v2 = xa[s2 * 8 + c]; float d2 = g_dis[s2];
        uint4 v3 = xa[s3 * 8 + c]; float d3 = g_dis[s3];
        p += 4;
        if (p + 3 < end) {
            s0 = g_csrs[p]; s1 = g_csrs[p + 1]; s2 = g_csrs[p + 2]; s3 = g_csrs[p + 3];
        }
        h8acc(v0, d0, acc);
        h8acc(v1, d1, acc);
        h8acc(v2, d2, acc);
        h8acc(v3, d3, acc);
    }
    for (; p < end; p++) {
        int s = g_csrs[p];
        h8acc(xa[s * 8 + c], g_dis[s], acc);
    }
}

// ---------------- launches #4,#5: fused gather + bias + relu + 64x64 GEMM ------
// Warp owns 4 nodes (8 lanes x 8 cols each). After ITS gather, the warp stages
// relu(dv*acc + bias) in a warp-private smem slab (__syncwarp only -- no block
// barrier, so no cross-node degree-tail coupling) and runs the GEMM itself.
// Output fp16 to fout.
__global__ __launch_bounds__(256) void k_gather_gemm(
    const __half* __restrict__ fin, __half* __restrict__ fout,
    const float* __restrict__ W, const float* __restrict__ bias_in, int n)
{
    __shared__ float Ws[64 * 64];                 // 16 KB
    __shared__ float bs[64];
    __shared__ float agg[8][4][68];               // warp-private slabs, padded

    int tid = threadIdx.x;
#pragma unroll
    for (int i = tid; i < 64 * 64 / 4; i += 256)
        ((float4*)Ws)[i] = ((const float4*)W)[i];
    if (tid < 16) ((float4*)bs)[tid] = ((const float4*)bias_in)[tid];
    __syncthreads();

    int w = tid >> 5;
    int g = (tid >> 3) & 3;
    int c = tid & 7;
    int node = blockIdx.x * 32 + (tid >> 3);
    bool ok = node < n;

    if (ok) {
        float dv = g_dis[node];
        float acc[8];
        gather8((const uint4*)fin, node, c, dv, acc);
        float* arow = agg[w][g];
        float4 v0 = make_float4(
            fmaxf(fmaf(acc[0], dv, bs[c * 8 + 0]), 0.f),
            fmaxf(fmaf(acc[1], dv, bs[c * 8 + 1]), 0.f),
            fmaxf(fmaf(acc[2], dv, bs[c * 8 + 2]), 0.f),
            fmaxf(fmaf(acc[3], dv, bs[c * 8 + 3]), 0.f));
        float4 v1 = make_float4(
            fmaxf(fmaf(acc[4], dv, bs[c * 8 + 4]), 0.f),
            fmaxf(fmaf(acc[5], dv, bs[c * 8 + 5]), 0.f),
            fmaxf(fmaf(acc[6], dv, bs[c * 8 + 6]), 0.f),
            fmaxf(fmaf(acc[7], dv, bs[c * 8 + 7]), 0.f));
        *(float4*)&arow[c * 8] = v0;
        *(float4*)&arow[c * 8 + 4] = v1;
    }
    __syncwarp();

    if (ok) {
        float o[8];
#pragma unroll
        for (int j = 0; j < 8; j++) o[j] = 0.f;
        const float* arow = agg[w][g];
#pragma unroll 4
        for (int k = 0; k < 64; k++) {
            float v = arow[k];                    // broadcast within node group
            const float* wr = &Ws[k * 64 + c * 8];
#pragma unroll
            for (int j = 0; j < 8; j++) o[j] = fmaf(v, wr[j], o[j]);
        }
        half2 h[4];
#pragma unroll
        for (int j = 0; j < 4; j++)
            h[j] = __float22half2_rn(make_float2(o[2 * j], o[2 * j + 1]));
        *(uint4*)(fout + (size_t)node * 64 + c * 8) = *(uint4*)&h[0];
    }
}

// ---------------- launch #6: fused gather + bias + relu + 64x8 head ------------
__global__ __launch_bounds__(256) void k_gather_final(
    const __half* __restrict__ fin, float* __restrict__ out,
    const float* __restrict__ linW, const float* __restrict__ b2,
    const float* __restrict__ linb, int n)
{
    __shared__ float Ws[64 * 8];
    __shared__ float bs[64];
    __shared__ float lb[8];
    __shared__ float agg[8][4][68];

    int tid = threadIdx.x;
#pragma unroll
    for (int i = tid; i < 128; i += 256) ((float4*)Ws)[i] = ((const float4*)linW)[i];
    if (tid < 16) ((float4*)bs)[tid] = ((const float4*)b2)[tid];
    if (tid < 2)  ((float4*)lb)[tid] = ((const float4*)linb)[tid];
    __syncthreads();

    int w = tid >> 5;
    int g = (tid >> 3) & 3;
    int c = tid & 7;
    int node = blockIdx.x * 32 + (tid >> 3);
    bool ok = node < n;

    if (ok) {
        float dv = g_dis[node];
        float acc[8];
        gather8((const uint4*)fin, node, c, dv, acc);
        float* arow = agg[w][g];
#pragma unroll
        for (int i = 0; i < 8; i++)
            arow[c * 8 + i] = fmaxf(fmaf(acc[i], dv, bs[c * 8 + i]), 0.f);
    }
    __syncwarp();

    if (ok) {
        const float* arow = agg[w][g];
        float o = lb[c];                           // lane c -> output col c
#pragma unroll 8
        for (int k = 0; k < 64; k++)
            o = fmaf(arow[k], Ws[k * 8 + c], o);
        out[(size_t)node * 8 + c] = o;
    }
}

// ---------------- host launcher ------------------------------------------------
extern "C" void kernel_launch(void* const* d_in, const int* in_sizes, int n_in,
                              void* d_out, int out_size)
{
    const float* x    = (const float*)d_in[0];
    const void*  ei   = d_in[1];
    const float* W0   = (const float*)d_in[2];
    const float* b0   = (const float*)d_in[3];
    const float* W1   = (const float*)d_in[4];
    const float* b1   = (const float*)d_in[5];
    const float* W2   = (const float*)d_in[6];
    const float* b2   = (const float*)d_in[7];
    const float* linW = (const float*)d_in[8];
    const float* linb = (const float*)d_in[9];
    float* out = (float*)d_out;

    int N = in_sizes[0] / DH;       // 50000
    int E = in_sizes[1] / 2;        // 800000

    const int T = 256;
    int gN = (N + T - 1) / T;       // 196
    int gE = (E + T - 1) / T;       // 3125
    int gA = (N + 31) / 32;         // 1563

    static __half* bufA = nullptr;
    static __half* bufC = nullptr;
    static int*    cntP = nullptr;
    if (!bufA) {
        void* p;
        cudaGetSymbolAddress(&p, g_bufA); bufA = (__half*)p;
        cudaGetSymbolAddress(&p, g_bufC); bufC = (__half*)p;
        cudaGetSymbolAddress(&p, g_cnt);  cntP = (int*)p;
    }
    cudaMemsetAsync(cntP, 0, (size_t)N * sizeof(int));

    // #1: fused layer-0 GEMM + histogram (+ per-edge slot)
    k_gemm0_hist<<<GEMM_BLOCKS + gE, T>>>(x, W0, ei, N, E);
    // #2: scan -> rowptr, dis
    k_scan<<<gN, SCAN_B>>>(N, E);
    // #3: CSR fill (no atomics)
    k_fill<<<gE, T>>>(ei, E);
    // #4: gather0 + relu(b0) + W1 GEMM   <-- ncu capture lands here
    k_gather_gemm<<<gA, T>>>(bufA, bufC, W1, b0, N);
    // #5: gather1 + relu(b1) + W2 GEMM
    k_gather_gemm<<<gA, T>>>(bufC, bufA, W2, b1, N);
    // #6: gather2 + relu(b2) + head
    k_gather_final<<<gA, T>>>(bufA, out, linW, b2, linb, N);
}

// round 13
// speedup vs baseline: 1.2433x; 1.0046x over previous
#include <cuda_runtime.h>
#include <cuda_fp16.h>
#include <stdint.h>

#define N_MAX 50000
#define E_MAX 800000
#define DH 64
#define SCAN_B 256
#define NBLK ((N_MAX + SCAN_B - 1) / SCAN_B)   // 196
#define GEMM_BLOCKS ((N_MAX + 63) / 64)        // 782

// ---------------- device scratch ---------------------------------------------
__device__ __align__(256) __half g_bufA[N_MAX * DH];  // fp16 features (ping)
__device__ __align__(256) __half g_bufC[N_MAX * DH];  // fp16 features (pong)
__device__ __align__(16)  float g_dis[N_MAX];
__device__ __align__(16)  int   g_cnt[N_MAX];
__device__ __align__(16)  int   g_rowptr[N_MAX + 1];
__device__ __align__(16)  int   g_look[NBLK];         // spin-scan mailbox
__device__ __align__(16)  int   g_slot[E_MAX];        // per-edge slot in its row
__device__ __align__(16)  int   g_csrs[E_MAX];        // CSR src indices

__device__ __forceinline__ bool detect64(const int* __restrict__ w) {
    int lane = threadIdx.x & 31;
    return __all_sync(0xffffffffu, w[2 * lane + 1] == 0);
}

// ---------------- launch #1: fused layer-0 GEMM + degree histogram -------------
__global__ __launch_bounds__(256) void k_gemm0_hist(
    const float* __restrict__ x, const float* __restrict__ W0,
    const void* __restrict__ ei, int n, int E)
{
    __shared__ float Ws[64 * 64];
    int tid = threadIdx.x;

    if (blockIdx.x < GEMM_BLOCKS) {
#pragma unroll
        for (int i = tid; i < 64 * 64 / 4; i += 256)
            ((float4*)Ws)[i] = ((const float4*)W0)[i];
        __syncthreads();

        int node = blockIdx.x * 64 + (tid >> 2);
        int quad = tid & 3;
        if (node >= n) return;

        float acc[16];
#pragma unroll
        for (int j = 0; j < 16; j++) acc[j] = 0.f;

        const float4* xr4 = (const float4*)(x + (size_t)node * 64);
        for (int k4 = 0; k4 < 16; k4++) {
            float4 v4 = xr4[k4];
            float vv[4] = {v4.x, v4.y, v4.z, v4.w};
#pragma unroll
            for (int u = 0; u < 4; u++) {
                const float* wrow = &Ws[(k4 * 4 + u) * 64 + quad * 16];
#pragma unroll
                for (int j = 0; j < 16; j++) acc[j] = fmaf(vv[u], wrow[j], acc[j]);
            }
        }
        half2 h[8];
#pragma unroll
        for (int j = 0; j < 8; j++)
            h[j] = __float22half2_rn(make_float2(acc[2 * j], acc[2 * j + 1]));
        uint4* op = (uint4*)(g_bufA + (size_t)node * 64 + quad * 16);
        op[0] = *(uint4*)&h[0];
        op[1] = *(uint4*)&h[4];
    } else {
        int b = blockIdx.x - GEMM_BLOCKS;
        bool is64 = detect64((const int*)ei);
        if (b == 0 && tid < NBLK) g_look[tid] = 0;
        int e = b * 256 + tid;
        if (e >= E) return;
        int d;
        if (is64) d = (int)((const long long*)ei)[e + E];
        else      d = ((const int*)ei)[e + E];
        g_slot[e] = atomicAdd(&g_cnt[d], 1);
    }
}

// ---------------- launch #2: single-kernel scan: rowptr, dis -------------------
__global__ __launch_bounds__(SCAN_B) void k_scan(int n, int E) {
    __shared__ int s[SCAN_B];
    int t = threadIdx.x, b = blockIdx.x;
    int i = b * SCAN_B + t;
    int v = (i < n) ? g_cnt[i] : 0;
    s[t] = v;
    __syncthreads();
#pragma unroll
    for (int off = 1; off < SCAN_B; off <<= 1) {
        int add = (t >= off) ? s[t - off] : 0;
        __syncthreads();
        s[t] += add;
        __syncthreads();
    }
    int excl = s[t] - v;
    int btotal = s[SCAN_B - 1];
    if (t == 0) atomicExch(&g_look[b], (1 << 29) | btotal);

    int contrib = 0;
    if (t < b) {
        int w;
        do { w = atomicAdd(&g_look[t], 0); } while (w == 0);
        contrib = w & 0x1FFFFFFF;
    }
    __syncthreads();
    s[t] = contrib;
    __syncthreads();
#pragma unroll
    for (int off = 128; off >= 1; off >>= 1) {
        if (t < off) s[t] += s[t + off];
        __syncthreads();
    }
    int base = s[0];

    if (i < n) {
        g_rowptr[i] = base + excl;
        g_dis[i] = rsqrtf((float)(v + 1));
    }
    if (b == 0 && t == 0) g_rowptr[n] = E;
}

// ---------------- launch #3: CSR fill (atomic-free) ----------------------------
__global__ void k_fill(const void* __restrict__ ei, int E) {
    const int* w = (const int*)ei;
    bool is64 = detect64(w);
    int e = blockIdx.x * blockDim.x + threadIdx.x;
    if (e >= E) return;
    int s, d;
    if (is64) {
        const long long* p = (const long long*)ei;
        s = (int)p[e];
        d = (int)p[e + E];
    } else {
        s = w[e];
        d = w[e + E];
    }
    g_csrs[g_rowptr[d] + g_slot[e]] = s;
}

// ---------------- fp16 helpers --------------------------------------------------
__device__ __forceinline__ void h8acc(uint4 u, float d, float acc[8]) {
    float2 f0 = __half22float2(*(const half2*)&u.x);
    float2 f1 = __half22float2(*(const half2*)&u.y);
    float2 f2 = __half22float2(*(const half2*)&u.z);
    float2 f3 = __half22float2(*(const half2*)&u.w);
    acc[0] = fmaf(f0.x, d, acc[0]); acc[1] = fmaf(f0.y, d, acc[1]);
    acc[2] = fmaf(f1.x, d, acc[2]); acc[3] = fmaf(f1.y, d, acc[3]);
    acc[4] = fmaf(f2.x, d, acc[4]); acc[5] = fmaf(f2.y, d, acc[5]);
    acc[6] = fmaf(f3.x, d, acc[6]); acc[7] = fmaf(f3.y, d, acc[7]);
}

__device__ __forceinline__ void gather8(
    const uint4* __restrict__ xa, int node, int c, float dv, float acc[8])
{
    uint4 me = xa[node * 8 + c];
    float2 f0 = __half22float2(*(const half2*)&me.x);
    float2 f1 = __half22float2(*(const half2*)&me.y);
    float2 f2 = __half22float2(*(const half2*)&me.z);
    float2 f3 = __half22float2(*(const half2*)&me.w);
    acc[0] = f0.x * dv; acc[1] = f0.y * dv;
    acc[2] = f1.x * dv; acc[3] = f1.y * dv;
    acc[4] = f2.x * dv; acc[5] = f2.y * dv;
    acc[6] = f3.x * dv; acc[7] = f3.y * dv;

    int p   = g_rowptr[node];
    int end = g_rowptr[node + 1];

    int s0 = 0, s1 = 0, s2 = 0, s3 = 0;
    if (p + 3 < end) {
        s0 = g_csrs[p]; s1 = g_csrs[p + 1]; s2 = g_csrs[p + 2]; s3 = g_csrs[p + 3];
    }
    while (p + 3 < end) {
        uint4 v0 = xa[s0 * 8 + c]; float d0 = g_dis[s0];
        uint4 v1 = xa[s1 * 8 + c]; float d1 = g_dis[s1];
        uint4 v2 = xa[s2 * 8 + c]; float d2 = g_dis[s2];
        uint4 v3 = xa[s3 * 8 + c]; float d3 = g_dis[s3];
        p += 4;
        if (p + 3 < end) {
            s0 = g_csrs[p]; s1 = g_csrs[p + 1]; s2 = g_csrs[p + 2]; s3 = g_csrs[p + 3];
        }
        h8acc(v0, d0, acc);
        h8acc(v1, d1, acc);
        h8acc(v2, d2, acc);
        h8acc(v3, d3, acc);
    }
    for (; p < end; p++) {
        int s = g_csrs[p];
        h8acc(xa[s * 8 + c], g_dis[s], acc);
    }
}

// ---------------- launches #4,#5: fused gather + bias + relu + 64x64 GEMM ------
// Warp owns 4 nodes (8 lanes x 8 cols). GEMM weight reads are float4 (LDS.128)
// — round-12 profile showed the scalar LDS.32 version saturating the smem
// crossbar (L1tex 82%, ~43us of conflict-serialized weight reads).
__global__ __launch_bounds__(256) void k_gather_gemm(
    const __half* __restrict__ fin, __half* __restrict__ fout,
    const float* __restrict__ W, const float* __restrict__ bias_in, int n)
{
    __shared__ float Ws[64 * 64];                 // 16 KB
    __shared__ float bs[64];
    __shared__ float agg[8][4][68];               // warp-private slabs, padded

    int tid = threadIdx.x;
#pragma unroll
    for (int i = tid; i < 64 * 64 / 4; i += 256)
        ((float4*)Ws)[i] = ((const float4*)W)[i];
    if (tid < 16) ((float4*)bs)[tid] = ((const float4*)bias_in)[tid];
    __syncthreads();

    int w = tid >> 5;
    int g = (tid >> 3) & 3;
    int c = tid & 7;
    int node = blockIdx.x * 32 + (tid >> 3);
    bool ok = node < n;

    if (ok) {
        float dv = g_dis[node];
        float acc[8];
        gather8((const uint4*)fin, node, c, dv, acc);
        float* arow = agg[w][g];
        float4 v0 = make_float4(
            fmaxf(fmaf(acc[0], dv, bs[c * 8 + 0]), 0.f),
            fmaxf(fmaf(acc[1], dv, bs[c * 8 + 1]), 0.f),
            fmaxf(fmaf(acc[2], dv, bs[c * 8 + 2]), 0.f),
            fmaxf(fmaf(acc[3], dv, bs[c * 8 + 3]), 0.f));
        float4 v1 = make_float4(
            fmaxf(fmaf(acc[4], dv, bs[c * 8 + 4]), 0.f),
            fmaxf(fmaf(acc[5], dv, bs[c * 8 + 5]), 0.f),
            fmaxf(fmaf(acc[6], dv, bs[c * 8 + 6]), 0.f),
            fmaxf(fmaf(acc[7], dv, bs[c * 8 + 7]), 0.f));
        *(float4*)&arow[c * 8] = v0;
        *(float4*)&arow[c * 8 + 4] = v1;
    }
    __syncwarp();

    if (ok) {
        float o[8];
#pragma unroll
        for (int j = 0; j < 8; j++) o[j] = 0.f;
        const float* arow = agg[w][g];
        const float4* wsp = (const float4*)&Ws[c * 8];   // row stride 16 float4s
#pragma unroll 8
        for (int k = 0; k < 64; k++) {
            float v = arow[k];                    // broadcast within node group
            float4 w0 = wsp[k * 16];              // LDS.128
            float4 w1 = wsp[k * 16 + 1];          // LDS.128
            o[0] = fmaf(v, w0.x, o[0]);
            o[1] = fmaf(v, w0.y, o[1]);
            o[2] = fmaf(v, w0.z, o[2]);
            o[3] = fmaf(v, w0.w, o[3]);
            o[4] = fmaf(v, w1.x, o[4]);
            o[5] = fmaf(v, w1.y, o[5]);
            o[6] = fmaf(v, w1.z, o[6]);
            o[7] = fmaf(v, w1.w, o[7]);
        }
        half2 h[4];
#pragma unroll
        for (int j = 0; j < 4; j++)
            h[j] = __float22half2_rn(make_float2(o[2 * j], o[2 * j + 1]));
        *(uint4*)(fout + (size_t)node * 64 + c * 8) = *(uint4*)&h[0];
    }
}

// ---------------- launch #6: fused gather + bias + relu + 64x8 head ------------
__global__ __launch_bounds__(256) void k_gather_final(
    const __half* __restrict__ fin, float* __restrict__ out,
    const float* __restrict__ linW, const float* __restrict__ b2,
    const float* __restrict__ linb, int n)
{
    __shared__ float Ws[64 * 8];
    __shared__ float bs[64];
    __shared__ float lb[8];
    __shared__ float agg[8][4][68];

    int tid = threadIdx.x;
#pragma unroll
    for (int i = tid; i < 128; i += 256) ((float4*)Ws)[i] = ((const float4*)linW)[i];
    if (tid < 16) ((float4*)bs)[tid] = ((const float4*)b2)[tid];
    if (tid < 2)  ((float4*)lb)[tid] = ((const float4*)linb)[tid];
    __syncthreads();

    int w = tid >> 5;
    int g = (tid >> 3) & 3;
    int c = tid & 7;
    int node = blockIdx.x * 32 + (tid >> 3);
    bool ok = node < n;

    if (ok) {
        float dv = g_dis[node];
        float acc[8];
        gather8((const uint4*)fin, node, c, dv, acc);
        float* arow = agg[w][g];
#pragma unroll
        for (int i = 0; i < 8; i++)
            arow[c * 8 + i] = fmaxf(fmaf(acc[i], dv, bs[c * 8 + i]), 0.f);
    }
    __syncwarp();

    if (ok) {
        const float* arow = agg[w][g];
        float o = lb[c];                           // lane c -> output col c
#pragma unroll 8
        for (int k = 0; k < 64; k++)
            o = fmaf(arow[k], Ws[k * 8 + c], o);   // conflict-free (8 banks)
        out[(size_t)node * 8 + c] = o;
    }
}

// ---------------- host launcher ------------------------------------------------
extern "C" void kernel_launch(void* const* d_in, const int* in_sizes, int n_in,
                              void* d_out, int out_size)
{
    const float* x    = (const float*)d_in[0];
    const void*  ei   = d_in[1];
    const float* W0   = (const float*)d_in[2];
    const float* b0   = (const float*)d_in[3];
    const float* W1   = (const float*)d_in[4];
    const float* b1   = (const float*)d_in[5];
    const float* W2   = (const float*)d_in[6];
    const float* b2   = (const float*)d_in[7];
    const float* linW = (const float*)d_in[8];
    const float* linb = (const float*)d_in[9];
    float* out = (float*)d_out;

    int N = in_sizes[0] / DH;       // 50000
    int E = in_sizes[1] / 2;        // 800000

    const int T = 256;
    int gN = (N + T - 1) / T;       // 196
    int gE = (E + T - 1) / T;       // 3125
    int gA = (N + 31) / 32;         // 1563

    static __half* bufA = nullptr;
    static __half* bufC = nullptr;
    static int*    cntP = nullptr;
    if (!bufA) {
        void* p;
        cudaGetSymbolAddress(&p, g_bufA); bufA = (__half*)p;
        cudaGetSymbolAddress(&p, g_bufC); bufC = (__half*)p;
        cudaGetSymbolAddress(&p, g_cnt);  cntP = (int*)p;
    }
    cudaMemsetAsync(cntP, 0, (size_t)N * sizeof(int));

    // #1: fused layer-0 GEMM + histogram (+ per-edge slot)
    k_gemm0_hist<<<GEMM_BLOCKS + gE, T>>>(x, W0, ei, N, E);
    // #2: scan -> rowptr, dis
    k_scan<<<gN, SCAN_B>>>(N, E);
    // #3: CSR fill (no atomics)
    k_fill<<<gE, T>>>(ei, E);
    // #4: gather0 + relu(b0) + W1 GEMM   <-- ncu capture lands here
    k_gather_gemm<<<gA, T>>>(bufA, bufC, W1, b0, N);
    // #5: gather1 + relu(b1) + W2 GEMM
    k_gather_gemm<<<gA, T>>>(bufC, bufA, W2, b1, N);
    // #6: gather2 + relu(b2) + head
    k_gather_final<<<gA, T>>>(bufA, out, linW, b2, linb, N);
}

// round 15
// speedup vs baseline: 1.7364x; 1.3966x over previous
#include <cuda_runtime.h>
#include <cuda_fp16.h>
#include <stdint.h>

#define N_MAX 50000
#define E_MAX 800000
#define DH 64
#define SCAN_B 256
#define NBLK ((N_MAX + SCAN_B - 1) / SCAN_B)   // 196
#define GEMM_BLOCKS ((N_MAX + 63) / 64)        // 782
#define WPAD 72   // padded weight row stride (floats): kills 2-way LDS conflicts

// ---------------- device scratch ---------------------------------------------
__device__ __align__(256) __half g_bufA[N_MAX * DH];  // fp16 features (ping)
__device__ __align__(256) __half g_bufC[N_MAX * DH];  // fp16 features (pong)
__device__ __align__(16)  float g_dis[N_MAX];
__device__ __align__(16)  int   g_cnt[N_MAX];
__device__ __align__(16)  int   g_rowptr[N_MAX + 1];
__device__ __align__(16)  int   g_look[NBLK];         // spin-scan mailbox
__device__ __align__(16)  int   g_slot[E_MAX];        // per-edge slot in its row
__device__ __align__(16)  int2  g_csr[E_MAX];         // (src, dis[src] as int)

__device__ __forceinline__ bool detect64(const int* __restrict__ w) {
    int lane = threadIdx.x & 31;
    return __all_sync(0xffffffffu, w[2 * lane + 1] == 0);
}

// ---------------- packed f32x2 FMA (sm_103a; ptxas never auto-fuses) ----------
#define FFMA2(acc, ab, w) \
    asm("fma.rn.f32x2 %0, %1, %2, %0;" : "+l"(acc) : "l"(ab), "l"(w))
#define PACK_FF(out, lo, hi) \
    asm("mov.b64 %0, {%1, %2};" : "=l"(out) : "f"(lo), "f"(hi))
#define UNPACK_FF(lo, hi, in) \
    asm("mov.b64 {%0, %1}, %2;" : "=f"(lo), "=f"(hi) : "l"(in))

// Copy a 64x64 row-major weight matrix into padded smem:
// Ws[k*WPAD + j + (j>=32 ? 4 : 0)]. 1024 float4s, stores stay 16B-aligned.
__device__ __forceinline__ void load_weights_padded(
    float* __restrict__ Ws, const float* __restrict__ W, int tid)
{
#pragma unroll
    for (int i = tid; i < 1024; i += 256) {
        float4 w4 = ((const float4*)W)[i];
        int k  = i >> 4;
        int j4 = (i & 15) * 4;
        *(float4*)&Ws[k * WPAD + j4 + ((j4 >= 32) ? 4 : 0)] = w4;
    }
}

// ---------------- launch #1: fused layer-0 GEMM + degree histogram -------------
__global__ __launch_bounds__(256) void k_gemm0_hist(
    const float* __restrict__ x, const float* __restrict__ W0,
    const void* __restrict__ ei, int n, int E)
{
    __shared__ float Ws[64 * WPAD];
    int tid = threadIdx.x;

    if (blockIdx.x < GEMM_BLOCKS) {
        load_weights_padded(Ws, W0, tid);
        __syncthreads();

        int node = blockIdx.x * 64 + (tid >> 2);
        int quad = tid & 3;
        if (node >= n) return;

        // quad reads cols quad*16..+15 (single half of the row each)
        const ulonglong2* wsp = (const ulonglong2*)
            &Ws[quad * 16 + ((quad >= 2) ? 4 : 0)];
        unsigned long long o2[8];
#pragma unroll
        for (int j = 0; j < 8; j++) o2[j] = 0ull;

        const float4* xr4 = (const float4*)(x + (size_t)node * 64);
        for (int k4 = 0; k4 < 16; k4++) {
            float4 v4 = xr4[k4];
            float vv[4] = {v4.x, v4.y, v4.z, v4.w};
#pragma unroll
            for (int u = 0; u < 4; u++) {
                unsigned long long vp;
                PACK_FF(vp, vv[u], vv[u]);
                const ulonglong2* row = wsp + (size_t)(k4 * 4 + u) * (WPAD / 4);
                ulonglong2 a = row[0], b = row[1], c2 = row[2], d2 = row[3];
                FFMA2(o2[0], vp, a.x);  FFMA2(o2[1], vp, a.y);
                FFMA2(o2[2], vp, b.x);  FFMA2(o2[3], vp, b.y);
                FFMA2(o2[4], vp, c2.x); FFMA2(o2[5], vp, c2.y);
                FFMA2(o2[6], vp, d2.x); FFMA2(o2[7], vp, d2.y);
            }
        }
        half2 h[8];
#pragma unroll
        for (int j = 0; j < 8; j++) {
            float lo, hi;
            UNPACK_FF(lo, hi, o2[j]);
            h[j] = __float22half2_rn(make_float2(lo, hi));
        }
        uint4* op = (uint4*)(g_bufA + (size_t)node * 64 + quad * 16);
        op[0] = *(uint4*)&h[0];
        op[1] = *(uint4*)&h[4];
    } else {
        int b = blockIdx.x - GEMM_BLOCKS;
        bool is64 = detect64((const int*)ei);
        if (b == 0 && tid < NBLK) g_look[tid] = 0;
        int e = b * 256 + tid;
        if (e >= E) return;
        int d;
        if (is64) d = (int)((const long long*)ei)[e + E];
        else      d = ((const int*)ei)[e + E];
        g_slot[e] = atomicAdd(&g_cnt[d], 1);
    }
}

// ---------------- launch #2: single-kernel scan: rowptr, dis -------------------
__global__ __launch_bounds__(SCAN_B) void k_scan(int n, int E) {
    __shared__ int s[SCAN_B];
    int t = threadIdx.x, b = blockIdx.x;
    int i = b * SCAN_B + t;
    int v = (i < n) ? g_cnt[i] : 0;
    s[t] = v;
    __syncthreads();
#pragma unroll
    for (int off = 1; off < SCAN_B; off <<= 1) {
        int add = (t >= off) ? s[t - off] : 0;
        __syncthreads();
        s[t] += add;
        __syncthreads();
    }
    int excl = s[t] - v;
    int btotal = s[SCAN_B - 1];
    if (t == 0) atomicExch(&g_look[b], (1 << 29) | btotal);

    int contrib = 0;
    if (t < b) {
        int w;
        do { w = atomicAdd(&g_look[t], 0); } while (w == 0);
        contrib = w & 0x1FFFFFFF;
    }
    __syncthreads();
    s[t] = contrib;
    __syncthreads();
#pragma unroll
    for (int off = 128; off >= 1; off >>= 1) {
        if (t < off) s[t] += s[t + off];
        __syncthreads();
    }
    int base = s[0];

    if (i < n) {
        g_rowptr[i] = base + excl;
        g_dis[i] = rsqrtf((float)(v + 1));
    }
    if (b == 0 && t == 0) g_rowptr[n] = E;
}

// ---------------- launch #3: CSR fill (atomic-free; packs dis[src]) ------------
__global__ void k_fill(const void* __restrict__ ei, int E) {
    const int* w = (const int*)ei;
    bool is64 = detect64(w);
    int e = blockIdx.x * blockDim.x + threadIdx.x;
    if (e >= E) return;
    int s, d;
    if (is64) {
        const long long* p = (const long long*)ei;
        s = (int)p[e];
        d = (int)p[e + E];
    } else {
        s = w[e];
        d = w[e + E];
    }
    g_csr[g_rowptr[d] + g_slot[e]] = make_int2(s, __float_as_int(g_dis[s]));
}

// ---------------- fp16 helpers --------------------------------------------------
__device__ __forceinline__ void h8acc(uint4 u, float d, float acc[8]) {
    float2 f0 = __half22float2(*(const half2*)&u.x);
    float2 f1 = __half22float2(*(const half2*)&u.y);
    float2 f2 = __half22float2(*(const half2*)&u.z);
    float2 f3 = __half22float2(*(const half2*)&u.w);
    acc[0] = fmaf(f0.x, d, acc[0]); acc[1] = fmaf(f0.y, d, acc[1]);
    acc[2] = fmaf(f1.x, d, acc[2]); acc[3] = fmaf(f1.y, d, acc[3]);
    acc[4] = fmaf(f2.x, d, acc[4]); acc[5] = fmaf(f2.y, d, acc[5]);
    acc[6] = fmaf(f3.x, d, acc[6]); acc[7] = fmaf(f3.y, d, acc[7]);
}

// Gather one node-column: acc = dv*xw[v] + sum_s dis[s]*xw[s], fp32 accum.
// CSR entries are (src, dis[src]) -- no dependent dis lookup in the hot loop.
__device__ __forceinline__ void gather8(
    const uint4* __restrict__ xa, int node, int c, float dv, float acc[8])
{
    uint4 me = xa[node * 8 + c];
    float2 f0 = __half22float2(*(const half2*)&me.x);
    float2 f1 = __half22float2(*(const half2*)&me.y);
    float2 f2 = __half22float2(*(const half2*)&me.z);
    float2 f3 = __half22float2(*(const half2*)&me.w);
    acc[0] = f0.x * dv; acc[1] = f0.y * dv;
    acc[2] = f1.x * dv; acc[3] = f1.y * dv;
    acc[4] = f2.x * dv; acc[5] = f2.y * dv;
    acc[6] = f3.x * dv; acc[7] = f3.y * dv;

    int p   = g_rowptr[node];
    int end = g_rowptr[node + 1];

    int2 e0, e1, e2, e3;
    if (p + 3 < end) {
        e0 = g_csr[p]; e1 = g_csr[p + 1]; e2 = g_csr[p + 2]; e3 = g_csr[p + 3];
    }
    while (p + 3 < end) {
        uint4 v0 = xa[e0.x * 8 + c];
        uint4 v1 = xa[e1.x * 8 + c];
        uint4 v2 = xa[e2.x * 8 + c];
        uint4 v3 = xa[e3.x * 8 + c];
        float d0 = __int_as_float(e0.y), d1 = __int_as_float(e1.y);
        float d2 = __int_as_float(e2.y), d3 = __int_as_float(e3.y);
        p += 4;
        if (p + 3 < end) {   // prefetch next batch
            e0 = g_csr[p]; e1 = g_csr[p + 1]; e2 = g_csr[p + 2]; e3 = g_csr[p + 3];
        }
        h8acc(v0, d0, acc);
        h8acc(v1, d1, acc);
        h8acc(v2, d2, acc);
        h8acc(v3, d3, acc);
    }
    for (; p < end; p++) {
        int2 e = g_csr[p];
        h8acc(xa[e.x * 8 + c], __int_as_float(e.y), acc);
    }
}

// ---------------- launches #4,#5: fused gather + bias + relu + 64x64 GEMM ------
// Warp owns 4 nodes (8 lanes x 8 cols). GEMM: padded conflict-free weight rows
// (single-phase LDS.128) + packed f32x2 FMA (half the FMA issue slots).
__global__ __launch_bounds__(256) void k_gather_gemm(
    const __half* __restrict__ fin, __half* __restrict__ fout,
    const float* __restrict__ W, const float* __restrict__ bias_in, int n)
{
    __shared__ float Ws[64 * WPAD];               // 18 KB
    __shared__ float bs[64];
    __shared__ float agg[8][4][68];               // warp-private slabs, padded

    int tid = threadIdx.x;
    load_weights_padded(Ws, W, tid);
    if (tid < 16) ((float4*)bs)[tid] = ((const float4*)bias_in)[tid];
    __syncthreads();

    int w = tid >> 5;
    int g = (tid >> 3) & 3;
    int c = tid & 7;
    int node = blockIdx.x * 32 + (tid >> 3);
    bool ok = node < n;

    if (ok) {
        float dv = g_dis[node];
        float acc[8];
        gather8((const uint4*)fin, node, c, dv, acc);
        float* arow = agg[w][g];
        float4 v0 = make_float4(
            fmaxf(fmaf(acc[0], dv, bs[c * 8 + 0]), 0.f),
            fmaxf(fmaf(acc[1], dv, bs[c * 8 + 1]), 0.f),
            fmaxf(fmaf(acc[2], dv, bs[c * 8 + 2]), 0.f),
            fmaxf(fmaf(acc[3], dv, bs[c * 8 + 3]), 0.f));
        float4 v1 = make_float4(
            fmaxf(fmaf(acc[4], dv, bs[c * 8 + 4]), 0.f),
            fmaxf(fmaf(acc[5], dv, bs[c * 8 + 5]), 0.f),
            fmaxf(fmaf(acc[6], dv, bs[c * 8 + 6]), 0.f),
            fmaxf(fmaf(acc[7], dv, bs[c * 8 + 7]), 0.f));
        *(float4*)&arow[c * 8] = v0;
        *(float4*)&arow[c * 8 + 4] = v1;
    }
    __syncwarp();

    if (ok) {
        unsigned long long o2[4];
#pragma unroll
        for (int j = 0; j < 4; j++) o2[j] = 0ull;
        const float* arow = agg[w][g];
        // lane c reads cols c*8..c*8+7 (one half of the padded row)
        const ulonglong2* wsp = (const ulonglong2*)
            &Ws[c * 8 + ((c >= 4) ? 4 : 0)];
#pragma unroll 8
        for (int k = 0; k < 64; k++) {
            float v = arow[k];                    // broadcast within node group
            unsigned long long vp;
            PACK_FF(vp, v, v);
            ulonglong2 wA = wsp[(size_t)k * (WPAD / 4)];       // LDS.128, 1 phase
            ulonglong2 wB = wsp[(size_t)k * (WPAD / 4) + 1];   // LDS.128, 1 phase
            FFMA2(o2[0], vp, wA.x);
            FFMA2(o2[1], vp, wA.y);
            FFMA2(o2[2], vp, wB.x);
            FFMA2(o2[3], vp, wB.y);
        }
        half2 h[4];
#pragma unroll
        for (int j = 0; j < 4; j++) {
            float lo, hi;
            UNPACK_FF(lo, hi, o2[j]);
            h[j] = __float22half2_rn(make_float2(lo, hi));
        }
        *(uint4*)(fout + (size_t)node * 64 + c * 8) = *(uint4*)&h[0];
    }
}

// ---------------- launch #6: fused gather + bias + relu + 64x8 head ------------
__global__ __launch_bounds__(256) void k_gather_final(
    const __half* __restrict__ fin, float* __restrict__ out,
    const float* __restrict__ linW, const float* __restrict__ b2,
    const float* __restrict__ linb, int n)
{
    __shared__ float Ws[64 * 8];
    __shared__ float bs[64];
    __shared__ float lb[8];
    __shared__ float agg[8][4][68];

    int tid = threadIdx.x;
#pragma unroll
    for (int i = tid; i < 128; i += 256) ((float4*)Ws)[i] = ((const float4*)linW)[i];
    if (tid < 16) ((float4*)bs)[tid] = ((const float4*)b2)[tid];
    if (tid < 2)  ((float4*)lb)[tid] = ((const float4*)linb)[tid];
    __syncthreads();

    int w = tid >> 5;
    int g = (tid >> 3) & 3;
    int c = tid & 7;
    int node = blockIdx.x * 32 + (tid >> 3);
    bool ok = node < n;

    if (ok) {
        float dv = g_dis[node];
        float acc[8];
        gather8((const uint4*)fin, node, c, dv, acc);
        float* arow = agg[w][g];
#pragma unroll
        for (int i = 0; i < 8; i++)
            arow[c * 8 + i] = fmaxf(fmaf(acc[i], dv, bs[c * 8 + i]), 0.f);
    }
    __syncwarp();

    if (ok) {
        const float* arow = agg[w][g];
        float o = lb[c];                           // lane c -> output col c
#pragma unroll 8
        for (int k = 0; k < 64; k++)
            o = fmaf(arow[k], Ws[k * 8 + c], o);   // conflict-free (8 banks)
        out[(size_t)node * 8 + c] = o;
    }
}

// ---------------- host launcher ------------------------------------------------
extern "C" void kernel_launch(void* const* d_in, const int* in_sizes, int n_in,
                              void* d_out, int out_size)
{
    const float* x    = (const float*)d_in[0];
    const void*  ei   = d_in[1];
    const float* W0   = (const float*)d_in[2];
    const float* b0   = (const float*)d_in[3];
    const float* W1   = (const float*)d_in[4];
    const float* b1   = (const float*)d_in[5];
    const float* W2   = (const float*)d_in[6];
    const float* b2   = (const float*)d_in[7];
    const float* linW = (const float*)d_in[8];
    const float* linb = (const float*)d_in[9];
    float* out = (float*)d_out;

    int N = in_sizes[0] / DH;       // 50000
    int E = in_sizes[1] / 2;        // 800000

    const int T = 256;
    int gN = (N + T - 1) / T;       // 196
    int gE = (E + T - 1) / T;       // 3125
    int gA = (N + 31) / 32;         // 1563

    static __half* bufA = nullptr;
    static __half* bufC = nullptr;
    static int*    cntP = nullptr;
    if (!bufA) {
        void* p;
        cudaGetSymbolAddress(&p, g_bufA); bufA = (__half*)p;
        cudaGetSymbolAddress(&p, g_bufC); bufC = (__half*)p;
        cudaGetSymbolAddress(&p, g_cnt);  cntP = (int*)p;
    }
    cudaMemsetAsync(cntP, 0, (size_t)N * sizeof(int));

    // #1: fused layer-0 GEMM + histogram (+ per-edge slot)
    k_gemm0_hist<<<GEMM_BLOCKS + gE, T>>>(x, W0, ei, N, E);
    // #2: scan -> rowptr, dis
    k_scan<<<gN, SCAN_B>>>(N, E);
    // #3: CSR fill (no atomics; packs dis[src])
    k_fill<<<gE, T>>>(ei, E);
    // #4: gather0 + relu(b0) + W1 GEMM   <-- ncu capture lands here
    k_gather_gemm<<<gA, T>>>(bufA, bufC, W1, b0, N);
    // #5: gather1 + relu(b1) + W2 GEMM
    k_gather_gemm<<<gA, T>>>(bufC, bufA, W2, b1, N);
    // #6: gather2 + relu(b2) + head
    k_gather_final<<<gA, T>>>(bufA, out, linW, b2, linb, N);
}